// round 13
// baseline (speedup 1.0000x reference)
#include <cuda_runtime.h>
#include <cuda_bf16.h>
#include <cstdint>

// ---------------------------------------------------------------------------
// SPMoEAdaptor: out = moe_b(moe_a(x)) + x
//   moe(x) = sum_e softmax(x@Wg)[:,e] * ((x - b_e) @ W_e)
// R12: fast path (bias==0, detected by prep) hoists gates-B before GEMM A via
// P = W_A,e @ WgB:  logits_B = h@WgB = sum_e gA_e (x@P_e). The inter-GEMM
// serial window shrinks to just the h repack. Fast/general split into
// separate loops so fold-only registers (gAf/gBf/wgB) don't burden the fast
// path. Everything else per R11: bf16 HMMA, cp.async x-stage, 384-thr CTA,
// work-stealing, streaming stores.
// ---------------------------------------------------------------------------

namespace {
// dynamic smem layout (bytes)
constexpr int SM_W    = 0;              // 64KB bf16 weights, both layers (n-major)
constexpr int SM_WGA  = 65536;          // 64 x float4 (w_gate_a as [d][e])
constexpr int SM_WGB  = 66560;
constexpr int SM_CA   = 67584;          // 64 x float4 (c_a as [f][e])
constexpr int SM_CB   = 68608;
constexpr int SM_P    = 69632;          // 64 x 16 fp32: P[d][e*4+j] = (W_A,e @ WgB)[d,j]
constexpr int SM_STAGE = 73728;         // 12 warps x 9216B x-stage
constexpr int STAGE_ROW  = 288;         // 256B data + 32B pad (bank-conflict-free)
constexpr int STAGE_WARP = 32 * STAGE_ROW;   // 9216
constexpr int SMEM_TOTAL = SM_STAGE + 12 * STAGE_WARP;  // 184320

constexpr int GRID = 148;               // 1 CTA per SM
}

// device-global scratch (allocation-free rule)
__device__ __align__(16) __nv_bfloat16 g_wswz[2][64 * 256];
__device__ __align__(16) float g_c[2][64 * 4];   // c[L][f*4+e] = (b_e @ W_e)[f]
__device__ __align__(16) float g_P[64 * 16];     // P[d][e*4+j]
__device__ unsigned g_unit_ctr;                  // work-stealing counter
__device__ int g_cflag;                          // 1 iff all c == 0 (fast path)

// ------------------------------- helpers ----------------------------------

__device__ __forceinline__ uint32_t smem_u32(const void* p) {
    uint32_t a;
    asm("{ .reg .u64 t; cvta.to.shared.u64 t, %1; cvt.u32.u64 %0, t; }" : "=r"(a) : "l"(p));
    return a;
}

__device__ __forceinline__ void ldsm_x4(uint32_t* r, uint32_t addr) {
    asm volatile("ldmatrix.sync.aligned.m8n8.x4.shared.b16 {%0,%1,%2,%3}, [%4];"
                 : "=r"(r[0]), "=r"(r[1]), "=r"(r[2]), "=r"(r[3]) : "r"(addr));
}

__device__ __forceinline__ void mma_bf16(float* d, const uint32_t* a,
                                         uint32_t b0, uint32_t b1) {
    asm volatile("mma.sync.aligned.m16n8k16.row.col.f32.bf16.bf16.f32 "
                 "{%0,%1,%2,%3}, {%4,%5,%6,%7}, {%8,%9}, {%0,%1,%2,%3};"
                 : "+f"(d[0]), "+f"(d[1]), "+f"(d[2]), "+f"(d[3])
                 : "r"(a[0]), "r"(a[1]), "r"(a[2]), "r"(a[3]), "r"(b0), "r"(b1));
}

__device__ __forceinline__ uint32_t pack_bf2(float lo, float hi) {
    __nv_bfloat162 t = __floats2bfloat162_rn(lo, hi);
    return *reinterpret_cast<uint32_t*>(&t);
}

__device__ __forceinline__ uint32_t bf2bcast(float v) { return pack_bf2(v, v); }

__device__ __forceinline__ uint32_t prmt(uint32_t a, uint32_t b, uint32_t sel) {
    uint32_t r;
    asm("prmt.b32 %0, %1, %2, %3;" : "=r"(r) : "r"(a), "r"(b), "r"(sel));
    return r;
}

__device__ __forceinline__ uint32_t hmul2u(uint32_t a, uint32_t b) {
    __nv_bfloat162 r = __hmul2(*reinterpret_cast<__nv_bfloat162*>(&a),
                               *reinterpret_cast<__nv_bfloat162*>(&b));
    return *reinterpret_cast<uint32_t*>(&r);
}

__device__ __forceinline__ float dot4(float4 a, float4 b) {
    return a.x * b.x + a.y * b.y + a.z * b.z + a.w * b.w;
}

__device__ __forceinline__ float4 softmax4(float4 l) {
    float mx = fmaxf(fmaxf(l.x, l.y), fmaxf(l.z, l.w));
    float e0 = __expf(l.x - mx), e1 = __expf(l.y - mx),
          e2 = __expf(l.z - mx), e3 = __expf(l.w - mx);
    float inv = 1.f / (e0 + e1 + e2 + e3);
    return make_float4(e0 * inv, e1 * inv, e2 * inv, e3 * inv);
}

__device__ __forceinline__ unsigned steal(int lane) {
    unsigned v = 0;
    if (lane == 0) v = atomicAdd(&g_unit_ctr, 1u);
    return __shfl_sync(0xffffffffu, v, 0);
}

__device__ __forceinline__ void issue_stage(const float* __restrict__ x, unsigned u,
                                            uint32_t dstbase, int lane) {
    const float* src = x + (size_t)u * 32 * 64;
    const int hl = lane >> 4;
    const int ch = lane & 15;
    #pragma unroll
    for (int i = 0; i < 16; i++) {
        int row = 2 * i + hl;
        uint32_t dst = dstbase + (uint32_t)(row * STAGE_ROW + ch * 16);
        const float* s = src + row * 64 + ch * 4;
        asm volatile("cp.async.cg.shared.global [%0], [%1], 16;" :: "r"(dst), "l"(s));
    }
    asm volatile("cp.async.commit_group;" ::: "memory");
}

__device__ __forceinline__ void stage_wait() {
    asm volatile("cp.async.wait_group 0;" ::: "memory");
    __syncwarp();
}

// one MoE GEMM layer: acc[2][8][4] += sum over e,kt of (g_e o A_frag) @ W_frag
__device__ __forceinline__ void run_layer(float acc[2][8][4],
                                          const uint32_t xf[2][4][4],
                                          const uint32_t g2[4][2][2],
                                          uint32_t wbase, int lane) {
    const int l7 = lane & 7;
    const uint32_t lane_row = (uint32_t)(((lane >> 4) & 1) * 8 + l7);
    const uint32_t kh = (uint32_t)((lane >> 3) & 1);
    const uint32_t lane_base = wbase + lane_row * 512u;
    #pragma unroll
    for (int e = 0; e < 4; e++) {
        #pragma unroll
        for (int kt = 0; kt < 4; kt++) {
            uint32_t a[2][4];
            #pragma unroll
            for (int m = 0; m < 2; m++) {
                a[m][0] = hmul2u(xf[m][kt][0], g2[e][m][0]);
                a[m][1] = hmul2u(xf[m][kt][1], g2[e][m][1]);
                a[m][2] = hmul2u(xf[m][kt][2], g2[e][m][0]);
                a[m][3] = hmul2u(xf[m][kt][3], g2[e][m][1]);
            }
            const uint32_t c0 = (uint32_t)(e * 8 + kt * 2) + kh;
            const uint32_t coff = ((c0 ^ (uint32_t)l7) << 4);
            #pragma unroll
            for (int np = 0; np < 4; np++) {
                uint32_t b[4];
                ldsm_x4(b, lane_base + (uint32_t)np * 8192u + coff);
                #pragma unroll
                for (int m = 0; m < 2; m++) {
                    mma_bf16(acc[m][2 * np],     a[m], b[0], b[1]);
                    mma_bf16(acc[m][2 * np + 1], a[m], b[2], b[3]);
                }
            }
        }
    }
}

// gates from A-fragments via tensor core (cols 4..7 duplicate experts 0..3).
__device__ __forceinline__ void gates_from_frags(const uint32_t xf[4][4],
                                                 const uint32_t* wg0,
                                                 const uint32_t* wg1,
                                                 int ql,
                                                 float4 gf[2],
                                                 uint32_t g2[4][2]) {
    float l[4]  = {0.f, 0.f, 0.f, 0.f};
    float l2[4] = {0.f, 0.f, 0.f, 0.f};
    mma_bf16(l,  xf[0], wg0[0], wg1[0]);
    mma_bf16(l2, xf[1], wg0[1], wg1[1]);
    mma_bf16(l,  xf[2], wg0[2], wg1[2]);
    mma_bf16(l2, xf[3], wg0[3], wg1[3]);
    l[0] += l2[0]; l[1] += l2[1]; l[2] += l2[2]; l[3] += l2[3];
    float r0 = __shfl_xor_sync(0xffffffffu, l[0], 1);
    float r1 = __shfl_xor_sync(0xffffffffu, l[1], 1);
    float r2 = __shfl_xor_sync(0xffffffffu, l[2], 1);
    float r3 = __shfl_xor_sync(0xffffffffu, l[3], 1);
    bool even = (ql & 1) == 0;
    float4 La = even ? make_float4(l[0], l[1], r0, r1)
                     : make_float4(r0, r1, l[0], l[1]);
    float4 Lb = even ? make_float4(l[2], l[3], r2, r3)
                     : make_float4(r2, r3, l[2], l[3]);
    float4 ga = softmax4(La);
    float4 gb = softmax4(Lb);
    gf[0] = ga; gf[1] = gb;
    g2[0][0] = bf2bcast(ga.x); g2[1][0] = bf2bcast(ga.y);
    g2[2][0] = bf2bcast(ga.z); g2[3][0] = bf2bcast(ga.w);
    g2[0][1] = bf2bcast(gb.x); g2[1][1] = bf2bcast(gb.y);
    g2[2][1] = bf2bcast(gb.z); g2[3][1] = bf2bcast(gb.w);
}

// ------------------------------- prep kernel ------------------------------

__global__ void prep_kernel(const float* __restrict__ wea, const float* __restrict__ bea,
                            const float* __restrict__ web, const float* __restrict__ beb,
                            const float* __restrict__ wgb) {
    int idx = blockIdx.x * blockDim.x + threadIdx.x;
    if (idx == 0) { g_unit_ctr = 0; g_cflag = 1; }
    if (idx < 2 * 4 * 64 * 64) {
        int L = idx >> 14;
        int r = idx & 16383;
        int e = r >> 12;
        int d = (r >> 6) & 63;
        int f = r & 63;
        const float* w = L ? web : wea;
        float v = w[(e * 64 + d) * 64 + f];
        int chunk = (e * 8 + (d >> 3)) ^ (f & 7);
        g_wswz[L][f * 256 + chunk * 8 + (d & 7)] = __float2bfloat16(v);
    }
    if (idx < 2 * 4 * 64) {
        int L = idx >> 8;
        int e = (idx >> 6) & 3;
        int f = idx & 63;
        const float* w = L ? web : wea;
        const float* b = L ? beb : bea;
        float s = 0.f;
        for (int d = 0; d < 64; d++)
            s += b[e * 64 + d] * w[(e * 64 + d) * 64 + f];
        g_c[L][f * 4 + e] = s;
        if (s != 0.f) atomicExch(&g_cflag, 0);
    }
    if (idx < 1024) {                    // P[d][e*4+j] = sum_f W_A[e][d][f] * WgB[f][j]
        int d = idx >> 4;
        int c = idx & 15;
        int e = c >> 2;
        int j = c & 3;
        float s = 0.f;
        for (int f = 0; f < 64; f++)
            s += wea[(e * 64 + d) * 64 + f] * wgb[f * 4 + j];
        g_P[d * 16 + c] = s;
    }
}

// ------------------------------- main kernel ------------------------------

__global__ void __launch_bounds__(384, 1)
moe_kernel(const float* __restrict__ x,
           const float* __restrict__ wg_a,
           const float* __restrict__ wg_b,
           float* __restrict__ out,
           int nunits_i) {
    extern __shared__ char smem[];
    const uint32_t sb = smem_u32(smem);
    const int tid  = threadIdx.x;
    const int lane = tid & 31;
    const int warp = tid >> 5;
    const unsigned nunits = (unsigned)nunits_i;

    // ---- one-time cooperative copies ----
    {
        const uint4* s0 = reinterpret_cast<const uint4*>(g_wswz);
        uint4* dW = reinterpret_cast<uint4*>(smem + SM_W);
        for (int i = tid; i < 4096; i += 384) dW[i] = s0[i];
        float* wga_s = reinterpret_cast<float*>(smem + SM_WGA);
        float* wgb_s = reinterpret_cast<float*>(smem + SM_WGB);
        float* ca_s  = reinterpret_cast<float*>(smem + SM_CA);
        float* cb_s  = reinterpret_cast<float*>(smem + SM_CB);
        if (tid < 256) {
            wga_s[tid] = wg_a[tid]; wgb_s[tid] = wg_b[tid];
            ca_s[tid]  = g_c[0][tid]; cb_s[tid] = g_c[1][tid];
        }
        float* p_s = reinterpret_cast<float*>(smem + SM_P);
        for (int i = tid; i < 1024; i += 384) p_s[i] = g_P[i];
    }
    const bool nofold = (g_cflag != 0);
    __syncthreads();

    const float4* CA4 = reinterpret_cast<const float4*>(smem + SM_CA);
    const float4* CB4 = reinterpret_cast<const float4*>(smem + SM_CB);

    const int ql = lane & 3;
    const int qr = lane >> 2;
    const char* stage = smem + SM_STAGE + warp * STAGE_WARP;
    const uint32_t stage_u32 = sb + (uint32_t)(SM_STAGE + warp * STAGE_WARP);

    // ---- gate-A Wg B-fragments (tile-invariant) ----
    uint32_t wgA0[4], wgA1[4];
    {
        const float* WGAf = reinterpret_cast<const float*>(smem + SM_WGA);
        const int e4 = qr & 3;
        #pragma unroll
        for (int kt = 0; kt < 4; kt++) {
            int d0 = kt * 16 + 2 * ql;
            wgA0[kt] = pack_bf2(WGAf[d0 * 4 + e4],       WGAf[(d0 + 1) * 4 + e4]);
            wgA1[kt] = pack_bf2(WGAf[(d0 + 8) * 4 + e4], WGAf[(d0 + 9) * 4 + e4]);
        }
    }

    if (nofold) {
        // ================= FAST PATH (bias == 0) =================
        // P fragments: col c = np*8 + qr, k pairs (2ql,2ql+1)/(+8,+9)
        uint32_t wgP0[2][4], wgP1[2][4];
        {
            const float* Pf = reinterpret_cast<const float*>(smem + SM_P);
            #pragma unroll
            for (int np = 0; np < 2; np++) {
                int c = np * 8 + qr;
                #pragma unroll
                for (int kt = 0; kt < 4; kt++) {
                    int d0 = kt * 16 + 2 * ql;
                    wgP0[np][kt] = pack_bf2(Pf[d0 * 16 + c],       Pf[(d0 + 1) * 16 + c]);
                    wgP1[np][kt] = pack_bf2(Pf[(d0 + 8) * 16 + c], Pf[(d0 + 9) * 16 + c]);
                }
            }
        }

        unsigned u = steal(lane);
        if (u < nunits) issue_stage(x, u, stage_u32, lane);

        while (u < nunits) {
            unsigned un = steal(lane);
            const size_t rowbase = (size_t)u * 32;

            stage_wait();

            // ---- X fragments from stage ----
            uint32_t xf[2][4][4];
            #pragma unroll
            for (int m = 0; m < 2; m++) {
                const char* r0p = stage + (m * 16 + qr) * STAGE_ROW;
                const char* r8p = r0p + 8 * STAGE_ROW;
                #pragma unroll
                for (int kt = 0; kt < 4; kt++) {
                    const int cb = (kt * 16 + ql * 2) * 4;
                    float2 f0 = *reinterpret_cast<const float2*>(r0p + cb);
                    float2 f1 = *reinterpret_cast<const float2*>(r8p + cb);
                    float2 f2 = *reinterpret_cast<const float2*>(r0p + cb + 32);
                    float2 f3 = *reinterpret_cast<const float2*>(r8p + cb + 32);
                    xf[m][kt][0] = pack_bf2(f0.x, f0.y);
                    xf[m][kt][1] = pack_bf2(f1.x, f1.y);
                    xf[m][kt][2] = pack_bf2(f2.x, f2.y);
                    xf[m][kt][3] = pack_bf2(f3.x, f3.y);
                }
            }

            // ---- gates A + t = x@P (independent MMA chains, interleavable) --
            float4 gAf[2][2];
            uint32_t gA2[4][2][2];
            float tt[2][2][4];
            #pragma unroll
            for (int m = 0; m < 2; m++) {
                float4 gf[2]; uint32_t g2c[4][2];
                gates_from_frags(xf[m], wgA0, wgA1, ql, gf, g2c);
                gAf[m][0] = gf[0]; gAf[m][1] = gf[1];
                #pragma unroll
                for (int e = 0; e < 4; e++) { gA2[e][m][0] = g2c[e][0]; gA2[e][m][1] = g2c[e][1]; }
                #pragma unroll
                for (int np = 0; np < 2; np++) {
                    tt[m][np][0] = 0.f; tt[m][np][1] = 0.f;
                    tt[m][np][2] = 0.f; tt[m][np][3] = 0.f;
                    #pragma unroll
                    for (int kt = 0; kt < 4; kt++)
                        mma_bf16(tt[m][np], xf[m][kt], wgP0[np][kt], wgP1[np][kt]);
                }
            }

            // ---- gates B from gA and t (before GEMM A) ----
            // lane's t cols: c = np*8+2ql+w ; e = (np? 2:0) + (ql>>1) ; j = c&3
            uint32_t gBpk[2][4];   // [m][e] = pack(gB_h0[e], gB_h1[e])
            const bool even = (ql & 1) == 0;
            const bool hiq  = (ql >> 1) != 0;
            #pragma unroll
            for (int m = 0; m < 2; m++) {
                #pragma unroll
                for (int h = 0; h < 2; h++) {
                    float4 g = gAf[m][h];
                    float gLo = hiq ? g.y : g.x;
                    float gHi = hiq ? g.w : g.z;
                    float a = gLo * tt[m][0][2*h]     + gHi * tt[m][1][2*h];
                    float b = gLo * tt[m][0][2*h + 1] + gHi * tt[m][1][2*h + 1];
                    a += __shfl_xor_sync(0xffffffffu, a, 2);
                    b += __shfl_xor_sync(0xffffffffu, b, 2);
                    float ra = __shfl_xor_sync(0xffffffffu, a, 1);
                    float rb = __shfl_xor_sync(0xffffffffu, b, 1);
                    float4 L = even ? make_float4(a, b, ra, rb)
                                    : make_float4(ra, rb, a, b);
                    float4 gb = softmax4(L);
                    if (h == 0) {
                        gBpk[m][0] = pack_bf2(gb.x, 0.f); gBpk[m][1] = pack_bf2(gb.y, 0.f);
                        gBpk[m][2] = pack_bf2(gb.z, 0.f); gBpk[m][3] = pack_bf2(gb.w, 0.f);
                    } else {
                        gBpk[m][0] = prmt(gBpk[m][0], pack_bf2(gb.x, gb.x), 0x5410u);
                        gBpk[m][1] = prmt(gBpk[m][1], pack_bf2(gb.y, gb.y), 0x5410u);
                        gBpk[m][2] = prmt(gBpk[m][2], pack_bf2(gb.z, gb.z), 0x5410u);
                        gBpk[m][3] = prmt(gBpk[m][3], pack_bf2(gb.w, gb.w), 0x5410u);
                    }
                }
            }

            // ---- layer A: acc = 0, GEMM ----
            float acc[2][8][4];
            #pragma unroll
            for (int n = 0; n < 8; n++)
                #pragma unroll
                for (int m = 0; m < 2; m++) {
                    acc[m][n][0] = 0.f; acc[m][n][1] = 0.f;
                    acc[m][n][2] = 0.f; acc[m][n][3] = 0.f;
                }
            run_layer(acc, xf, gA2, sb + SM_W, lane);

            // ---- repack h (only serial work between GEMMs) ----
            #pragma unroll
            for (int m = 0; m < 2; m++)
                #pragma unroll
                for (int kt = 0; kt < 4; kt++) {
                    xf[m][kt][0] = pack_bf2(acc[m][2*kt][0],   acc[m][2*kt][1]);
                    xf[m][kt][1] = pack_bf2(acc[m][2*kt][2],   acc[m][2*kt][3]);
                    xf[m][kt][2] = pack_bf2(acc[m][2*kt+1][0], acc[m][2*kt+1][1]);
                    xf[m][kt][3] = pack_bf2(acc[m][2*kt+1][2], acc[m][2*kt+1][3]);
                }

            // ---- expand packed gB -> bcast pairs ----
            uint32_t gB2[4][2][2];
            #pragma unroll
            for (int m = 0; m < 2; m++)
                #pragma unroll
                for (int e = 0; e < 4; e++) {
                    gB2[e][m][0] = prmt(gBpk[m][e], gBpk[m][e], 0x1010u);
                    gB2[e][m][1] = prmt(gBpk[m][e], gBpk[m][e], 0x3232u);
                }

            // ---- layer B: acc = residual, GEMM ----
            #pragma unroll
            for (int n = 0; n < 8; n++) {
                int c = n * 8 + ql * 2;
                #pragma unroll
                for (int m = 0; m < 2; m++) {
                    const char* rlp = stage + (m * 16 + qr) * STAGE_ROW + c * 4;
                    float2 xl = *reinterpret_cast<const float2*>(rlp);
                    float2 xh = *reinterpret_cast<const float2*>(rlp + 8 * STAGE_ROW);
                    acc[m][n][0] = xl.x; acc[m][n][1] = xl.y;
                    acc[m][n][2] = xh.x; acc[m][n][3] = xh.y;
                }
            }
            __syncwarp();
            if (un < nunits) issue_stage(x, un, stage_u32, lane);

            run_layer(acc, xf, gB2, sb + SM_W + 32768, lane);

            // ---- epilogue ----
            #pragma unroll
            for (int m = 0; m < 2; m++) {
                const size_t rl = rowbase + (size_t)(m * 16 + qr);
                const size_t rh = rl + 8;
                #pragma unroll
                for (int n = 0; n < 8; n++) {
                    int c = n * 8 + ql * 2;
                    __stcs(reinterpret_cast<float2*>(out + rl * 64 + c),
                           make_float2(acc[m][n][0], acc[m][n][1]));
                    __stcs(reinterpret_cast<float2*>(out + rh * 64 + c),
                           make_float2(acc[m][n][2], acc[m][n][3]));
                }
            }

            u = un;
        }
    } else {
        // ================= GENERAL PATH (nonzero bias; R11 body) ============
        uint32_t wgB0[4], wgB1[4];
        {
            const float* WGBf = reinterpret_cast<const float*>(smem + SM_WGB);
            const int e4 = qr & 3;
            #pragma unroll
            for (int kt = 0; kt < 4; kt++) {
                int d0 = kt * 16 + 2 * ql;
                wgB0[kt] = pack_bf2(WGBf[d0 * 4 + e4],       WGBf[(d0 + 1) * 4 + e4]);
                wgB1[kt] = pack_bf2(WGBf[(d0 + 8) * 4 + e4], WGBf[(d0 + 9) * 4 + e4]);
            }
        }

        unsigned u = steal(lane);
        if (u < nunits) issue_stage(x, u, stage_u32, lane);

        while (u < nunits) {
            unsigned un = steal(lane);
            const size_t rowbase = (size_t)u * 32;

            stage_wait();

            uint32_t xf[2][4][4];
            #pragma unroll
            for (int m = 0; m < 2; m++) {
                const char* r0p = stage + (m * 16 + qr) * STAGE_ROW;
                const char* r8p = r0p + 8 * STAGE_ROW;
                #pragma unroll
                for (int kt = 0; kt < 4; kt++) {
                    const int cb = (kt * 16 + ql * 2) * 4;
                    float2 f0 = *reinterpret_cast<const float2*>(r0p + cb);
                    float2 f1 = *reinterpret_cast<const float2*>(r8p + cb);
                    float2 f2 = *reinterpret_cast<const float2*>(r0p + cb + 32);
                    float2 f3 = *reinterpret_cast<const float2*>(r8p + cb + 32);
                    xf[m][kt][0] = pack_bf2(f0.x, f0.y);
                    xf[m][kt][1] = pack_bf2(f1.x, f1.y);
                    xf[m][kt][2] = pack_bf2(f2.x, f2.y);
                    xf[m][kt][3] = pack_bf2(f3.x, f3.y);
                }
            }

            float4 gAf[2][2];
            uint32_t gA2[4][2][2];
            #pragma unroll
            for (int m = 0; m < 2; m++) {
                float4 gf[2]; uint32_t g2c[4][2];
                gates_from_frags(xf[m], wgA0, wgA1, ql, gf, g2c);
                gAf[m][0] = gf[0]; gAf[m][1] = gf[1];
                #pragma unroll
                for (int e = 0; e < 4; e++) { gA2[e][m][0] = g2c[e][0]; gA2[e][m][1] = g2c[e][1]; }
            }

            float acc[2][8][4];
            #pragma unroll
            for (int n = 0; n < 8; n++) {
                int c = n * 8 + ql * 2;
                float4 c0 = CA4[c], c1 = CA4[c + 1];
                #pragma unroll
                for (int m = 0; m < 2; m++) {
                    acc[m][n][0] = -dot4(gAf[m][0], c0);
                    acc[m][n][1] = -dot4(gAf[m][0], c1);
                    acc[m][n][2] = -dot4(gAf[m][1], c0);
                    acc[m][n][3] = -dot4(gAf[m][1], c1);
                }
            }
            run_layer(acc, xf, gA2, sb + SM_W, lane);

            #pragma unroll
            for (int m = 0; m < 2; m++)
                #pragma unroll
                for (int kt = 0; kt < 4; kt++) {
                    xf[m][kt][0] = pack_bf2(acc[m][2*kt][0],   acc[m][2*kt][1]);
                    xf[m][kt][1] = pack_bf2(acc[m][2*kt][2],   acc[m][2*kt][3]);
                    xf[m][kt][2] = pack_bf2(acc[m][2*kt+1][0], acc[m][2*kt+1][1]);
                    xf[m][kt][3] = pack_bf2(acc[m][2*kt+1][2], acc[m][2*kt+1][3]);
                }

            float4 gBf[2][2];
            uint32_t gB2[4][2][2];
            #pragma unroll
            for (int m = 0; m < 2; m++) {
                float4 gf[2]; uint32_t g2c[4][2];
                gates_from_frags(xf[m], wgB0, wgB1, ql, gf, g2c);
                gBf[m][0] = gf[0]; gBf[m][1] = gf[1];
                #pragma unroll
                for (int e = 0; e < 4; e++) { gB2[e][m][0] = g2c[e][0]; gB2[e][m][1] = g2c[e][1]; }
            }

            #pragma unroll
            for (int n = 0; n < 8; n++) {
                int c = n * 8 + ql * 2;
                float4 c0 = CB4[c], c1 = CB4[c + 1];
                #pragma unroll
                for (int m = 0; m < 2; m++) {
                    const char* rlp = stage + (m * 16 + qr) * STAGE_ROW + c * 4;
                    float2 xl = *reinterpret_cast<const float2*>(rlp);
                    float2 xh = *reinterpret_cast<const float2*>(rlp + 8 * STAGE_ROW);
                    acc[m][n][0] = xl.x - dot4(gBf[m][0], c0);
                    acc[m][n][1] = xl.y - dot4(gBf[m][0], c1);
                    acc[m][n][2] = xh.x - dot4(gBf[m][1], c0);
                    acc[m][n][3] = xh.y - dot4(gBf[m][1], c1);
                }
            }

            __syncwarp();
            if (un < nunits) issue_stage(x, un, stage_u32, lane);

            run_layer(acc, xf, gB2, sb + SM_W + 32768, lane);

            #pragma unroll
            for (int m = 0; m < 2; m++) {
                const size_t rl = rowbase + (size_t)(m * 16 + qr);
                const size_t rh = rl + 8;
                #pragma unroll
                for (int n = 0; n < 8; n++) {
                    int c = n * 8 + ql * 2;
                    __stcs(reinterpret_cast<float2*>(out + rl * 64 + c),
                           make_float2(acc[m][n][0], acc[m][n][1]));
                    __stcs(reinterpret_cast<float2*>(out + rh * 64 + c),
                           make_float2(acc[m][n][2], acc[m][n][3]));
                }
            }

            u = un;
        }
    }
}

// ------------------------------- launch -----------------------------------

extern "C" void kernel_launch(void* const* d_in, const int* in_sizes, int n_in,
                              void* d_out, int out_size) {
    const float* x   = (const float*)d_in[0];
    const float* wga = (const float*)d_in[1];
    const float* wea = (const float*)d_in[2];
    const float* bea = (const float*)d_in[3];
    const float* wgb = (const float*)d_in[4];
    const float* web = (const float*)d_in[5];
    const float* beb = (const float*)d_in[6];
    float* out = (float*)d_out;

    const int ntok   = in_sizes[0] / 64;
    const int nunits = ntok / 32;

    prep_kernel<<<64, 512>>>(wea, bea, web, beb, wgb);

    cudaFuncSetAttribute(moe_kernel, cudaFuncAttributeMaxDynamicSharedMemorySize, SMEM_TOTAL);
    moe_kernel<<<GRID, 384, SMEM_TOTAL>>>(x, wga, wgb, out, nunits);
}

// round 14
// speedup vs baseline: 1.0575x; 1.0575x over previous
#include <cuda_runtime.h>
#include <cuda_bf16.h>
#include <cstdint>

// ---------------------------------------------------------------------------
// SPMoEAdaptor: out = moe_b(moe_a(x)) + x
//   moe(x) = sum_e softmax(x@Wg)[:,e] * ((x - b_e) @ W_e)
// R13: R11 semantics (bf16 HMMA, cp.async x-stage, 384-thr CTA, work-steal,
// zero-bias fast path) with register-slack scheduling: fast/general split
// into separate loops, fast gates never materialize float4 gate vectors
// (~32 regs freed below the 170 cap), and run_layer batches all 4 ldsm per
// (e,kt) (MLP=4) with the hmul2 scaling filling the LDS wait. No new work.
// ---------------------------------------------------------------------------

namespace {
// dynamic smem layout (bytes)
constexpr int SM_W    = 0;              // 64KB bf16 weights, both layers (n-major)
constexpr int SM_WGA  = 65536;          // 64 x float4 (w_gate_a as [d][e])
constexpr int SM_WGB  = 66560;
constexpr int SM_CA   = 67584;          // 64 x float4 (c_a as [f][e])
constexpr int SM_CB   = 68608;
constexpr int SM_STAGE = 69632;         // 12 warps x 9216B x-stage
constexpr int STAGE_ROW  = 288;         // 256B data + 32B pad (bank-conflict-free)
constexpr int STAGE_WARP = 32 * STAGE_ROW;   // 9216
constexpr int SMEM_TOTAL = SM_STAGE + 12 * STAGE_WARP;  // 180224

constexpr int GRID = 148;               // 1 CTA per SM
}

// device-global scratch (allocation-free rule)
__device__ __align__(16) __nv_bfloat16 g_wswz[2][64 * 256];
__device__ __align__(16) float g_c[2][64 * 4];   // c[L][f*4+e] = (b_e @ W_e)[f]
__device__ unsigned g_unit_ctr;                  // work-stealing counter
__device__ int g_cflag;                          // 1 iff all c == 0 (fast path)

// ------------------------------- helpers ----------------------------------

__device__ __forceinline__ uint32_t smem_u32(const void* p) {
    uint32_t a;
    asm("{ .reg .u64 t; cvta.to.shared.u64 t, %1; cvt.u32.u64 %0, t; }" : "=r"(a) : "l"(p));
    return a;
}

__device__ __forceinline__ void ldsm_x4(uint32_t* r, uint32_t addr) {
    asm volatile("ldmatrix.sync.aligned.m8n8.x4.shared.b16 {%0,%1,%2,%3}, [%4];"
                 : "=r"(r[0]), "=r"(r[1]), "=r"(r[2]), "=r"(r[3]) : "r"(addr));
}

__device__ __forceinline__ void mma_bf16(float* d, const uint32_t* a,
                                         uint32_t b0, uint32_t b1) {
    asm volatile("mma.sync.aligned.m16n8k16.row.col.f32.bf16.bf16.f32 "
                 "{%0,%1,%2,%3}, {%4,%5,%6,%7}, {%8,%9}, {%0,%1,%2,%3};"
                 : "+f"(d[0]), "+f"(d[1]), "+f"(d[2]), "+f"(d[3])
                 : "r"(a[0]), "r"(a[1]), "r"(a[2]), "r"(a[3]), "r"(b0), "r"(b1));
}

__device__ __forceinline__ uint32_t pack_bf2(float lo, float hi) {
    __nv_bfloat162 t = __floats2bfloat162_rn(lo, hi);
    return *reinterpret_cast<uint32_t*>(&t);
}

__device__ __forceinline__ uint32_t bf2bcast(float v) { return pack_bf2(v, v); }

__device__ __forceinline__ uint32_t hmul2u(uint32_t a, uint32_t b) {
    __nv_bfloat162 r = __hmul2(*reinterpret_cast<__nv_bfloat162*>(&a),
                               *reinterpret_cast<__nv_bfloat162*>(&b));
    return *reinterpret_cast<uint32_t*>(&r);
}

__device__ __forceinline__ float dot4(float4 a, float4 b) {
    return a.x * b.x + a.y * b.y + a.z * b.z + a.w * b.w;
}

__device__ __forceinline__ float4 softmax4(float4 l) {
    float mx = fmaxf(fmaxf(l.x, l.y), fmaxf(l.z, l.w));
    float e0 = __expf(l.x - mx), e1 = __expf(l.y - mx),
          e2 = __expf(l.z - mx), e3 = __expf(l.w - mx);
    float inv = 1.f / (e0 + e1 + e2 + e3);
    return make_float4(e0 * inv, e1 * inv, e2 * inv, e3 * inv);
}

__device__ __forceinline__ unsigned steal(int lane) {
    unsigned v = 0;
    if (lane == 0) v = atomicAdd(&g_unit_ctr, 1u);
    return __shfl_sync(0xffffffffu, v, 0);
}

__device__ __forceinline__ void issue_stage(const float* __restrict__ x, unsigned u,
                                            uint32_t dstbase, int lane) {
    const float* src = x + (size_t)u * 32 * 64;
    const int hl = lane >> 4;
    const int ch = lane & 15;
    #pragma unroll
    for (int i = 0; i < 16; i++) {
        int row = 2 * i + hl;
        uint32_t dst = dstbase + (uint32_t)(row * STAGE_ROW + ch * 16);
        const float* s = src + row * 64 + ch * 4;
        asm volatile("cp.async.cg.shared.global [%0], [%1], 16;" :: "r"(dst), "l"(s));
    }
    asm volatile("cp.async.commit_group;" ::: "memory");
}

__device__ __forceinline__ void stage_wait() {
    asm volatile("cp.async.wait_group 0;" ::: "memory");
    __syncwarp();
}

// one MoE GEMM layer, batched-ldsm form: per (e,kt) issue all 4 ldsm.x4
// (MLP=4), then the 8 hmul2 scalings (fills LDS wait), then 16 MMAs.
__device__ __forceinline__ void run_layer(float acc[2][8][4],
                                          const uint32_t xf[2][4][4],
                                          const uint32_t g2[4][2][2],
                                          uint32_t wbase, int lane) {
    const int l7 = lane & 7;
    const uint32_t lane_row = (uint32_t)(((lane >> 4) & 1) * 8 + l7);
    const uint32_t kh = (uint32_t)((lane >> 3) & 1);
    const uint32_t lane_base = wbase + lane_row * 512u;
    #pragma unroll
    for (int e = 0; e < 4; e++) {
        #pragma unroll
        for (int kt = 0; kt < 4; kt++) {
            const uint32_t c0 = (uint32_t)(e * 8 + kt * 2) + kh;
            const uint32_t coff = ((c0 ^ (uint32_t)l7) << 4);
            uint32_t bb[4][4];
            #pragma unroll
            for (int np = 0; np < 4; np++)
                ldsm_x4(bb[np], lane_base + (uint32_t)np * 8192u + coff);
            uint32_t a[2][4];
            #pragma unroll
            for (int m = 0; m < 2; m++) {
                a[m][0] = hmul2u(xf[m][kt][0], g2[e][m][0]);
                a[m][1] = hmul2u(xf[m][kt][1], g2[e][m][1]);
                a[m][2] = hmul2u(xf[m][kt][2], g2[e][m][0]);
                a[m][3] = hmul2u(xf[m][kt][3], g2[e][m][1]);
            }
            #pragma unroll
            for (int np = 0; np < 4; np++) {
                mma_bf16(acc[0][2 * np],     a[0], bb[np][0], bb[np][1]);
                mma_bf16(acc[0][2 * np + 1], a[0], bb[np][2], bb[np][3]);
                mma_bf16(acc[1][2 * np],     a[1], bb[np][0], bb[np][1]);
                mma_bf16(acc[1][2 * np + 1], a[1], bb[np][2], bb[np][3]);
            }
        }
    }
}

// fast-path gates: tensor-core logits -> softmax -> bcast pairs ONLY
// (no float4 gate vector kept live).
__device__ __forceinline__ void gates_b2(const uint32_t xf[4][4],
                                         const uint32_t* wg0,
                                         const uint32_t* wg1,
                                         int ql,
                                         uint32_t g2[4][2]) {
    float l[4]  = {0.f, 0.f, 0.f, 0.f};
    float l2[4] = {0.f, 0.f, 0.f, 0.f};
    mma_bf16(l,  xf[0], wg0[0], wg1[0]);
    mma_bf16(l2, xf[1], wg0[1], wg1[1]);
    mma_bf16(l,  xf[2], wg0[2], wg1[2]);
    mma_bf16(l2, xf[3], wg0[3], wg1[3]);
    l[0] += l2[0]; l[1] += l2[1]; l[2] += l2[2]; l[3] += l2[3];
    float r0 = __shfl_xor_sync(0xffffffffu, l[0], 1);
    float r1 = __shfl_xor_sync(0xffffffffu, l[1], 1);
    float r2 = __shfl_xor_sync(0xffffffffu, l[2], 1);
    float r3 = __shfl_xor_sync(0xffffffffu, l[3], 1);
    bool even = (ql & 1) == 0;
    float4 La = even ? make_float4(l[0], l[1], r0, r1)
                     : make_float4(r0, r1, l[0], l[1]);
    float4 Lb = even ? make_float4(l[2], l[3], r2, r3)
                     : make_float4(r2, r3, l[2], l[3]);
    float4 ga = softmax4(La);
    float4 gb = softmax4(Lb);
    g2[0][0] = bf2bcast(ga.x); g2[1][0] = bf2bcast(ga.y);
    g2[2][0] = bf2bcast(ga.z); g2[3][0] = bf2bcast(ga.w);
    g2[0][1] = bf2bcast(gb.x); g2[1][1] = bf2bcast(gb.y);
    g2[2][1] = bf2bcast(gb.z); g2[3][1] = bf2bcast(gb.w);
}

// general-path gates: also returns float4 gate vectors for the bias folds.
__device__ __forceinline__ void gates_from_frags(const uint32_t xf[4][4],
                                                 const uint32_t* wg0,
                                                 const uint32_t* wg1,
                                                 int ql,
                                                 float4 gf[2],
                                                 uint32_t g2[4][2]) {
    float l[4]  = {0.f, 0.f, 0.f, 0.f};
    float l2[4] = {0.f, 0.f, 0.f, 0.f};
    mma_bf16(l,  xf[0], wg0[0], wg1[0]);
    mma_bf16(l2, xf[1], wg0[1], wg1[1]);
    mma_bf16(l,  xf[2], wg0[2], wg1[2]);
    mma_bf16(l2, xf[3], wg0[3], wg1[3]);
    l[0] += l2[0]; l[1] += l2[1]; l[2] += l2[2]; l[3] += l2[3];
    float r0 = __shfl_xor_sync(0xffffffffu, l[0], 1);
    float r1 = __shfl_xor_sync(0xffffffffu, l[1], 1);
    float r2 = __shfl_xor_sync(0xffffffffu, l[2], 1);
    float r3 = __shfl_xor_sync(0xffffffffu, l[3], 1);
    bool even = (ql & 1) == 0;
    float4 La = even ? make_float4(l[0], l[1], r0, r1)
                     : make_float4(r0, r1, l[0], l[1]);
    float4 Lb = even ? make_float4(l[2], l[3], r2, r3)
                     : make_float4(r2, r3, l[2], l[3]);
    float4 ga = softmax4(La);
    float4 gb = softmax4(Lb);
    gf[0] = ga; gf[1] = gb;
    g2[0][0] = bf2bcast(ga.x); g2[1][0] = bf2bcast(ga.y);
    g2[2][0] = bf2bcast(ga.z); g2[3][0] = bf2bcast(ga.w);
    g2[0][1] = bf2bcast(gb.x); g2[1][1] = bf2bcast(gb.y);
    g2[2][1] = bf2bcast(gb.z); g2[3][1] = bf2bcast(gb.w);
}

// ------------------------------- prep kernel ------------------------------

__global__ void prep_kernel(const float* __restrict__ wea, const float* __restrict__ bea,
                            const float* __restrict__ web, const float* __restrict__ beb) {
    int idx = blockIdx.x * blockDim.x + threadIdx.x;
    if (idx == 0) { g_unit_ctr = 0; g_cflag = 1; }
    if (idx < 2 * 4 * 64 * 64) {
        int L = idx >> 14;
        int r = idx & 16383;
        int e = r >> 12;
        int d = (r >> 6) & 63;
        int f = r & 63;
        const float* w = L ? web : wea;
        float v = w[(e * 64 + d) * 64 + f];
        int chunk = (e * 8 + (d >> 3)) ^ (f & 7);
        g_wswz[L][f * 256 + chunk * 8 + (d & 7)] = __float2bfloat16(v);
    }
    if (idx < 2 * 4 * 64) {
        int L = idx >> 8;
        int e = (idx >> 6) & 3;
        int f = idx & 63;
        const float* w = L ? web : wea;
        const float* b = L ? beb : bea;
        float s = 0.f;
        for (int d = 0; d < 64; d++)
            s += b[e * 64 + d] * w[(e * 64 + d) * 64 + f];
        g_c[L][f * 4 + e] = s;
        if (s != 0.f) atomicExch(&g_cflag, 0);
    }
}

// ------------------------------- main kernel ------------------------------

__global__ void __launch_bounds__(384, 1)
moe_kernel(const float* __restrict__ x,
           const float* __restrict__ wg_a,
           const float* __restrict__ wg_b,
           float* __restrict__ out,
           int nunits_i) {
    extern __shared__ char smem[];
    const uint32_t sb = smem_u32(smem);
    const int tid  = threadIdx.x;
    const int lane = tid & 31;
    const int warp = tid >> 5;
    const unsigned nunits = (unsigned)nunits_i;

    // ---- one-time cooperative copies ----
    {
        const uint4* s0 = reinterpret_cast<const uint4*>(g_wswz);
        uint4* dW = reinterpret_cast<uint4*>(smem + SM_W);
        for (int i = tid; i < 4096; i += 384) dW[i] = s0[i];
        float* wga_s = reinterpret_cast<float*>(smem + SM_WGA);
        float* wgb_s = reinterpret_cast<float*>(smem + SM_WGB);
        float* ca_s  = reinterpret_cast<float*>(smem + SM_CA);
        float* cb_s  = reinterpret_cast<float*>(smem + SM_CB);
        if (tid < 256) {
            wga_s[tid] = wg_a[tid]; wgb_s[tid] = wg_b[tid];
            ca_s[tid]  = g_c[0][tid]; cb_s[tid] = g_c[1][tid];
        }
    }
    const bool nofold = (g_cflag != 0);
    __syncthreads();

    const int ql = lane & 3;
    const int qr = lane >> 2;
    const char* stage = smem + SM_STAGE + warp * STAGE_WARP;
    const uint32_t stage_u32 = sb + (uint32_t)(SM_STAGE + warp * STAGE_WARP);

    // ---- gate-A Wg B-fragments (tile-invariant) ----
    uint32_t wgA0[4], wgA1[4], wgB0[4], wgB1[4];
    {
        const float* WGAf = reinterpret_cast<const float*>(smem + SM_WGA);
        const float* WGBf = reinterpret_cast<const float*>(smem + SM_WGB);
        const int e4 = qr & 3;
        #pragma unroll
        for (int kt = 0; kt < 4; kt++) {
            int d0 = kt * 16 + 2 * ql;
            wgA0[kt] = pack_bf2(WGAf[d0 * 4 + e4],       WGAf[(d0 + 1) * 4 + e4]);
            wgA1[kt] = pack_bf2(WGAf[(d0 + 8) * 4 + e4], WGAf[(d0 + 9) * 4 + e4]);
            wgB0[kt] = pack_bf2(WGBf[d0 * 4 + e4],       WGBf[(d0 + 1) * 4 + e4]);
            wgB1[kt] = pack_bf2(WGBf[(d0 + 8) * 4 + e4], WGBf[(d0 + 9) * 4 + e4]);
        }
    }

    if (nofold) {
        // ================= FAST PATH (bias == 0) =================
        unsigned u = steal(lane);
        if (u < nunits) issue_stage(x, u, stage_u32, lane);

        while (u < nunits) {
            unsigned un = steal(lane);
            const size_t rowbase = (size_t)u * 32;

            stage_wait();

            // ---- X fragments from stage ----
            uint32_t xf[2][4][4];
            #pragma unroll
            for (int m = 0; m < 2; m++) {
                const char* r0p = stage + (m * 16 + qr) * STAGE_ROW;
                const char* r8p = r0p + 8 * STAGE_ROW;
                #pragma unroll
                for (int kt = 0; kt < 4; kt++) {
                    const int cb = (kt * 16 + ql * 2) * 4;
                    float2 f0 = *reinterpret_cast<const float2*>(r0p + cb);
                    float2 f1 = *reinterpret_cast<const float2*>(r8p + cb);
                    float2 f2 = *reinterpret_cast<const float2*>(r0p + cb + 32);
                    float2 f3 = *reinterpret_cast<const float2*>(r8p + cb + 32);
                    xf[m][kt][0] = pack_bf2(f0.x, f0.y);
                    xf[m][kt][1] = pack_bf2(f1.x, f1.y);
                    xf[m][kt][2] = pack_bf2(f2.x, f2.y);
                    xf[m][kt][3] = pack_bf2(f3.x, f3.y);
                }
            }

            // ---- gates A (bcast pairs only) ----
            uint32_t gA2[4][2][2];
            #pragma unroll
            for (int m = 0; m < 2; m++) {
                uint32_t g2c[4][2];
                gates_b2(xf[m], wgA0, wgA1, ql, g2c);
                #pragma unroll
                for (int e = 0; e < 4; e++) { gA2[e][m][0] = g2c[e][0]; gA2[e][m][1] = g2c[e][1]; }
            }

            // ---- layer A: acc = 0, GEMM ----
            float acc[2][8][4];
            #pragma unroll
            for (int n = 0; n < 8; n++)
                #pragma unroll
                for (int m = 0; m < 2; m++) {
                    acc[m][n][0] = 0.f; acc[m][n][1] = 0.f;
                    acc[m][n][2] = 0.f; acc[m][n][3] = 0.f;
                }
            run_layer(acc, xf, gA2, sb + SM_W, lane);

            // ---- repack h: C-frag layout == A-frag layout (per kt) ----
            #pragma unroll
            for (int m = 0; m < 2; m++)
                #pragma unroll
                for (int kt = 0; kt < 4; kt++) {
                    xf[m][kt][0] = pack_bf2(acc[m][2*kt][0],   acc[m][2*kt][1]);
                    xf[m][kt][1] = pack_bf2(acc[m][2*kt][2],   acc[m][2*kt][3]);
                    xf[m][kt][2] = pack_bf2(acc[m][2*kt+1][0], acc[m][2*kt+1][1]);
                    xf[m][kt][3] = pack_bf2(acc[m][2*kt+1][2], acc[m][2*kt+1][3]);
                }

            // ---- gates B (bcast pairs only) ----
            uint32_t gB2[4][2][2];
            #pragma unroll
            for (int m = 0; m < 2; m++) {
                uint32_t g2c[4][2];
                gates_b2(xf[m], wgB0, wgB1, ql, g2c);
                #pragma unroll
                for (int e = 0; e < 4; e++) { gB2[e][m][0] = g2c[e][0]; gB2[e][m][1] = g2c[e][1]; }
            }

            // ---- layer B: acc = residual (from stage), GEMM ----
            #pragma unroll
            for (int n = 0; n < 8; n++) {
                int c = n * 8 + ql * 2;
                #pragma unroll
                for (int m = 0; m < 2; m++) {
                    const char* rlp = stage + (m * 16 + qr) * STAGE_ROW + c * 4;
                    float2 xl = *reinterpret_cast<const float2*>(rlp);
                    float2 xh = *reinterpret_cast<const float2*>(rlp + 8 * STAGE_ROW);
                    acc[m][n][0] = xl.x; acc[m][n][1] = xl.y;
                    acc[m][n][2] = xh.x; acc[m][n][3] = xh.y;
                }
            }
            __syncwarp();
            if (un < nunits) issue_stage(x, un, stage_u32, lane);

            run_layer(acc, xf, gB2, sb + SM_W + 32768, lane);

            // ---- epilogue: pure streaming stores ----
            #pragma unroll
            for (int m = 0; m < 2; m++) {
                const size_t rl = rowbase + (size_t)(m * 16 + qr);
                const size_t rh = rl + 8;
                #pragma unroll
                for (int n = 0; n < 8; n++) {
                    int c = n * 8 + ql * 2;
                    __stcs(reinterpret_cast<float2*>(out + rl * 64 + c),
                           make_float2(acc[m][n][0], acc[m][n][1]));
                    __stcs(reinterpret_cast<float2*>(out + rh * 64 + c),
                           make_float2(acc[m][n][2], acc[m][n][3]));
                }
            }

            u = un;
        }
    } else {
        // ================= GENERAL PATH (nonzero bias) =================
        const float4* CA4 = reinterpret_cast<const float4*>(smem + SM_CA);
        const float4* CB4 = reinterpret_cast<const float4*>(smem + SM_CB);

        unsigned u = steal(lane);
        if (u < nunits) issue_stage(x, u, stage_u32, lane);

        while (u < nunits) {
            unsigned un = steal(lane);
            const size_t rowbase = (size_t)u * 32;

            stage_wait();

            uint32_t xf[2][4][4];
            #pragma unroll
            for (int m = 0; m < 2; m++) {
                const char* r0p = stage + (m * 16 + qr) * STAGE_ROW;
                const char* r8p = r0p + 8 * STAGE_ROW;
                #pragma unroll
                for (int kt = 0; kt < 4; kt++) {
                    const int cb = (kt * 16 + ql * 2) * 4;
                    float2 f0 = *reinterpret_cast<const float2*>(r0p + cb);
                    float2 f1 = *reinterpret_cast<const float2*>(r8p + cb);
                    float2 f2 = *reinterpret_cast<const float2*>(r0p + cb + 32);
                    float2 f3 = *reinterpret_cast<const float2*>(r8p + cb + 32);
                    xf[m][kt][0] = pack_bf2(f0.x, f0.y);
                    xf[m][kt][1] = pack_bf2(f1.x, f1.y);
                    xf[m][kt][2] = pack_bf2(f2.x, f2.y);
                    xf[m][kt][3] = pack_bf2(f3.x, f3.y);
                }
            }

            float4 gAf[2][2];
            uint32_t gA2[4][2][2];
            #pragma unroll
            for (int m = 0; m < 2; m++) {
                float4 gf[2]; uint32_t g2c[4][2];
                gates_from_frags(xf[m], wgA0, wgA1, ql, gf, g2c);
                gAf[m][0] = gf[0]; gAf[m][1] = gf[1];
                #pragma unroll
                for (int e = 0; e < 4; e++) { gA2[e][m][0] = g2c[e][0]; gA2[e][m][1] = g2c[e][1]; }
            }

            float acc[2][8][4];
            #pragma unroll
            for (int n = 0; n < 8; n++) {
                int c = n * 8 + ql * 2;
                float4 c0 = CA4[c], c1 = CA4[c + 1];
                #pragma unroll
                for (int m = 0; m < 2; m++) {
                    acc[m][n][0] = -dot4(gAf[m][0], c0);
                    acc[m][n][1] = -dot4(gAf[m][0], c1);
                    acc[m][n][2] = -dot4(gAf[m][1], c0);
                    acc[m][n][3] = -dot4(gAf[m][1], c1);
                }
            }
            run_layer(acc, xf, gA2, sb + SM_W, lane);

            #pragma unroll
            for (int m = 0; m < 2; m++)
                #pragma unroll
                for (int kt = 0; kt < 4; kt++) {
                    xf[m][kt][0] = pack_bf2(acc[m][2*kt][0],   acc[m][2*kt][1]);
                    xf[m][kt][1] = pack_bf2(acc[m][2*kt][2],   acc[m][2*kt][3]);
                    xf[m][kt][2] = pack_bf2(acc[m][2*kt+1][0], acc[m][2*kt+1][1]);
                    xf[m][kt][3] = pack_bf2(acc[m][2*kt+1][2], acc[m][2*kt+1][3]);
                }

            float4 gBf[2][2];
            uint32_t gB2[4][2][2];
            #pragma unroll
            for (int m = 0; m < 2; m++) {
                float4 gf[2]; uint32_t g2c[4][2];
                gates_from_frags(xf[m], wgB0, wgB1, ql, gf, g2c);
                gBf[m][0] = gf[0]; gBf[m][1] = gf[1];
                #pragma unroll
                for (int e = 0; e < 4; e++) { gB2[e][m][0] = g2c[e][0]; gB2[e][m][1] = g2c[e][1]; }
            }

            #pragma unroll
            for (int n = 0; n < 8; n++) {
                int c = n * 8 + ql * 2;
                float4 c0 = CB4[c], c1 = CB4[c + 1];
                #pragma unroll
                for (int m = 0; m < 2; m++) {
                    const char* rlp = stage + (m * 16 + qr) * STAGE_ROW + c * 4;
                    float2 xl = *reinterpret_cast<const float2*>(rlp);
                    float2 xh = *reinterpret_cast<const float2*>(rlp + 8 * STAGE_ROW);
                    acc[m][n][0] = xl.x - dot4(gBf[m][0], c0);
                    acc[m][n][1] = xl.y - dot4(gBf[m][0], c1);
                    acc[m][n][2] = xh.x - dot4(gBf[m][1], c0);
                    acc[m][n][3] = xh.y - dot4(gBf[m][1], c1);
                }
            }

            __syncwarp();
            if (un < nunits) issue_stage(x, un, stage_u32, lane);

            run_layer(acc, xf, gB2, sb + SM_W + 32768, lane);

            #pragma unroll
            for (int m = 0; m < 2; m++) {
                const size_t rl = rowbase + (size_t)(m * 16 + qr);
                const size_t rh = rl + 8;
                #pragma unroll
                for (int n = 0; n < 8; n++) {
                    int c = n * 8 + ql * 2;
                    __stcs(reinterpret_cast<float2*>(out + rl * 64 + c),
                           make_float2(acc[m][n][0], acc[m][n][1]));
                    __stcs(reinterpret_cast<float2*>(out + rh * 64 + c),
                           make_float2(acc[m][n][2], acc[m][n][3]));
                }
            }

            u = un;
        }
    }
}

// ------------------------------- launch -----------------------------------

extern "C" void kernel_launch(void* const* d_in, const int* in_sizes, int n_in,
                              void* d_out, int out_size) {
    const float* x   = (const float*)d_in[0];
    const float* wga = (const float*)d_in[1];
    const float* wea = (const float*)d_in[2];
    const float* bea = (const float*)d_in[3];
    const float* wgb = (const float*)d_in[4];
    const float* web = (const float*)d_in[5];
    const float* beb = (const float*)d_in[6];
    float* out = (float*)d_out;

    const int ntok   = in_sizes[0] / 64;
    const int nunits = ntok / 32;

    prep_kernel<<<64, 512>>>(wea, bea, web, beb);

    cudaFuncSetAttribute(moe_kernel, cudaFuncAttributeMaxDynamicSharedMemorySize, SMEM_TOTAL);
    moe_kernel<<<GRID, 384, SMEM_TOTAL>>>(x, wga, wgb, out, nunits);
}